// round 1
// baseline (speedup 1.0000x reference)
#include <cuda_runtime.h>
#include <cstdint>

// Problem constants (fixed shapes from reference: B=64, S=512, D=512)
#define Bn 64
#define Sn 512
#define Dn 512
#define BS (Bn * Sn)

// ---------------- scratch (device globals; no allocations allowed) ----------
__device__ unsigned g_rowmax[BS];   // ordered-uint encoded max over valid j, per (b,i)
__device__ unsigned g_colmax[BS];   // ordered-uint encoded max over valid i, per (b,j)
__device__ float    g_inv[2 * BS];  // 1/||token||: first BS for emb1, next BS for emb2
__device__ int      g_len[2 * Bn];  // n1[b], then n2[b]

// ordered encoding: monotonic float -> uint, so atomicMax(unsigned) == float max
__device__ __forceinline__ unsigned encf(float x) {
    unsigned u = __float_as_uint(x);
    return (u & 0x80000000u) ? ~u : (u | 0x80000000u);
}
__device__ __forceinline__ float decf(unsigned u) {
    return (u & 0x80000000u) ? __uint_as_float(u ^ 0x80000000u)
                             : __uint_as_float(~u);
}

// ---------------- kernel 1: init max buffers + per-batch lengths -------------
// grid: 256 blocks x 256 threads. Blocks 0..127 additionally reduce one mask row.
__global__ void prep_kernel(const int* __restrict__ mask1,
                            const int* __restrict__ mask2) {
    int tid = threadIdx.x;
    int gid = blockIdx.x * blockDim.x + tid;
    if (gid < BS) { g_rowmax[gid] = 0u; g_colmax[gid] = 0u; }  // 0 < enc(any float)

    if (blockIdx.x < 2 * Bn) {
        const int* row = (blockIdx.x < Bn) ? (mask1 + blockIdx.x * Sn)
                                           : (mask2 + (blockIdx.x - Bn) * Sn);
        int s = row[tid] + row[tid + 256];
        // block reduce (256 threads)
        __shared__ int sh[256];
        sh[tid] = s;
        __syncthreads();
        for (int off = 128; off > 0; off >>= 1) {
            if (tid < off) sh[tid] += sh[tid + off];
            __syncthreads();
        }
        if (tid == 0) g_len[blockIdx.x] = sh[0];
    }
}

// ---------------- kernel 2: inverse L2 norms (one warp per token) ------------
// tokens: 2*B*S = 65536; 8 warps/block -> 8192 blocks
__global__ void norm_kernel(const float* __restrict__ e1,
                            const float* __restrict__ e2) {
    int warp = blockIdx.x * 8 + (threadIdx.x >> 5);
    int lane = threadIdx.x & 31;
    const float* p = (warp < BS) ? (e1 + (size_t)warp * Dn)
                                 : (e2 + (size_t)(warp - BS) * Dn);
    float ss = 0.f;
    const float4* p4 = (const float4*)p;
#pragma unroll
    for (int i = 0; i < 4; i++) {
        float4 v = p4[i * 32 + lane];
        ss += v.x * v.x + v.y * v.y + v.z * v.z + v.w * v.w;
    }
#pragma unroll
    for (int off = 16; off > 0; off >>= 1)
        ss += __shfl_xor_sync(0xffffffffu, ss, off);
    if (lane == 0) g_inv[warp] = 1.0f / fmaxf(sqrtf(ss), 1e-8f);
}

// ---------------- kernel 3: tiled sim GEMM + masked row/col max --------------
// 64x64 output tile, K-step 16, 256 threads, 4x4 per thread.
// grid: (j_tiles=8, i_tiles=8, B=64). Early-exit fully-masked tiles.
__global__ __launch_bounds__(256) void sim_kernel(const float* __restrict__ e1,
                                                  const float* __restrict__ e2) {
    const int b  = blockIdx.z;
    const int bi = blockIdx.y;
    const int bj = blockIdx.x;
    const int n1 = g_len[b];
    const int n2 = g_len[Bn + b];
    const int i0 = bi * 64, j0 = bj * 64;
    if (i0 >= n1 || j0 >= n2) return;

    __shared__ float As[16][64];
    __shared__ float Bs[16][64];
    __shared__ unsigned srow[64], scol[64];

    const int tid = threadIdx.x;
    const float* A  = e1 + (size_t)b * Sn * Dn + (size_t)i0 * Dn;
    const float* Bp = e2 + (size_t)b * Sn * Dn + (size_t)j0 * Dn;

    // load mapping: thread -> (row = tid/4 in 0..63, kofs = (tid%4)*4)
    const int lr = tid >> 2;
    const int lc = (tid & 3) * 4;

    const int trow = (tid >> 4) * 4;   // 0..60
    const int tcol = (tid & 15) * 4;   // 0..60

    float acc[4][4];
#pragma unroll
    for (int r = 0; r < 4; r++)
#pragma unroll
        for (int c = 0; c < 4; c++) acc[r][c] = 0.f;

    for (int k0 = 0; k0 < Dn; k0 += 16) {
        float4 a4 = *(const float4*)(A  + (size_t)lr * Dn + k0 + lc);
        float4 b4 = *(const float4*)(Bp + (size_t)lr * Dn + k0 + lc);
        __syncthreads();
        As[lc + 0][lr] = a4.x; As[lc + 1][lr] = a4.y;
        As[lc + 2][lr] = a4.z; As[lc + 3][lr] = a4.w;
        Bs[lc + 0][lr] = b4.x; Bs[lc + 1][lr] = b4.y;
        Bs[lc + 2][lr] = b4.z; Bs[lc + 3][lr] = b4.w;
        __syncthreads();
#pragma unroll
        for (int k = 0; k < 16; k++) {
            float4 av = *(const float4*)&As[k][trow];
            float4 bv = *(const float4*)&Bs[k][tcol];
            float a[4] = {av.x, av.y, av.z, av.w};
            float bb[4] = {bv.x, bv.y, bv.z, bv.w};
#pragma unroll
            for (int r = 0; r < 4; r++)
#pragma unroll
                for (int c = 0; c < 4; c++) acc[r][c] = fmaf(a[r], bb[c], acc[r][c]);
        }
    }

    // ---- epilogue: scale by inverse norms, masked row/col maxes ----
    if (tid < 64) { srow[tid] = 0u; scol[tid] = 0u; }
    __syncthreads();

    float inv_i[4], inv_j[4];
#pragma unroll
    for (int r = 0; r < 4; r++) inv_i[r] = g_inv[b * Sn + i0 + trow + r];
#pragma unroll
    for (int c = 0; c < 4; c++) inv_j[c] = g_inv[BS + b * Sn + j0 + tcol + c];

    unsigned rmax[4] = {0u, 0u, 0u, 0u};
    unsigned cmax[4] = {0u, 0u, 0u, 0u};
#pragma unroll
    for (int r = 0; r < 4; r++) {
        int i = i0 + trow + r;
        bool iv = (i < n1);
#pragma unroll
        for (int c = 0; c < 4; c++) {
            int j = j0 + tcol + c;
            if (iv && j < n2) {
                unsigned e = encf(acc[r][c] * inv_i[r] * inv_j[c]);
                rmax[r] = max(rmax[r], e);
                cmax[c] = max(cmax[c], e);
            }
        }
    }
#pragma unroll
    for (int r = 0; r < 4; r++)
        if (rmax[r]) atomicMax(&srow[trow + r], rmax[r]);
#pragma unroll
    for (int c = 0; c < 4; c++)
        if (cmax[c]) atomicMax(&scol[tcol + c], cmax[c]);
    __syncthreads();

    if (tid < 64) {
        int i = i0 + tid;
        if (i < n1 && srow[tid]) atomicMax(&g_rowmax[b * Sn + i], srow[tid]);
    } else if (tid < 128) {
        int t = tid - 64;
        int j = j0 + t;
        if (j < n2 && scol[t]) atomicMax(&g_colmax[b * Sn + j], scol[t]);
    }
}

// ---------------- kernel 4: per-batch reduction ------------------------------
__global__ void reduce_kernel(float* __restrict__ out) {
    int b = blockIdx.x;
    int tid = threadIdx.x;
    int n1 = g_len[b], n2 = g_len[Bn + b];
    float s = 0.f;
    for (int i = tid; i < n1; i += 256) s += decf(g_rowmax[b * Sn + i]);
    for (int j = tid; j < n2; j += 256) s += decf(g_colmax[b * Sn + j]);
    __shared__ float sh[256];
    sh[tid] = s;
    __syncthreads();
    for (int off = 128; off > 0; off >>= 1) {
        if (tid < off) sh[tid] += sh[tid + off];
        __syncthreads();
    }
    if (tid == 0) out[b] = sh[0] / (float)(n1 + n2);
}

// ---------------- launch -----------------------------------------------------
extern "C" void kernel_launch(void* const* d_in, const int* in_sizes, int n_in,
                              void* d_out, int out_size) {
    const float* e1 = (const float*)d_in[0];
    const float* e2 = (const float*)d_in[1];
    const int* m1 = (const int*)d_in[2];
    const int* m2 = (const int*)d_in[3];
    float* out = (float*)d_out;

    prep_kernel<<<256, 256>>>(m1, m2);
    norm_kernel<<<(2 * BS) / 8, 256>>>(e1, e2);
    dim3 grid(Sn / 64, Sn / 64, Bn);
    sim_kernel<<<grid, 256>>>(e1, e2);
    reduce_kernel<<<Bn, 256>>>(out);
}

// round 3
// speedup vs baseline: 2.6490x; 2.6490x over previous
#include <cuda_runtime.h>
#include <cuda_fp16.h>
#include <cstdint>

// Problem constants (fixed shapes: B=64, S=512, D=512)
#define Bn 64
#define Sn 512
#define Dn 512
#define BS (Bn * Sn)

// ---------------- scratch (device globals; no allocations allowed) ----------
__device__ unsigned g_rowmax[BS];       // ordered-uint max over valid j per (b,i)
__device__ unsigned g_colmax[BS];       // ordered-uint max over valid i per (b,j)
__device__ int      g_len[2 * Bn];      // n1[b], then n2[b]
__device__ __half   g_hA[BS * Dn];      // normalized e1, fp16 (32MB)
__device__ __half   g_hB[BS * Dn];      // normalized e2, fp16 (32MB)

// ordered encoding: monotonic float -> uint, so atomicMax(unsigned) == float max
__device__ __forceinline__ unsigned encf(float x) {
    unsigned u = __float_as_uint(x);
    return (u & 0x80000000u) ? ~u : (u | 0x80000000u);
}
__device__ __forceinline__ float decf(unsigned u) {
    return (u & 0x80000000u) ? __uint_as_float(u ^ 0x80000000u)
                             : __uint_as_float(~u);
}

// ---------------- async-copy / mma helpers (sm_80+ PTX, compute_103-safe) ----
__device__ __forceinline__ uint32_t smem_u32(const void* p) {
    uint32_t a;
    asm("{ .reg .u64 t; cvta.to.shared.u64 t, %1; cvt.u32.u64 %0, t; }"
        : "=r"(a) : "l"(p));
    return a;
}
__device__ __forceinline__ void cp16(uint32_t s, const void* g) {
    asm volatile("cp.async.ca.shared.global [%0], [%1], 16;" :: "r"(s), "l"(g));
}
#define CP_COMMIT() asm volatile("cp.async.commit_group;" ::: "memory")
#define CP_WAIT(N)  asm volatile("cp.async.wait_group %0;" :: "n"(N) : "memory")

__device__ __forceinline__ void ldm_x4(uint32_t& r0, uint32_t& r1,
                                       uint32_t& r2, uint32_t& r3, uint32_t a) {
    asm volatile("ldmatrix.sync.aligned.m8n8.x4.shared.b16 {%0,%1,%2,%3}, [%4];"
                 : "=r"(r0), "=r"(r1), "=r"(r2), "=r"(r3) : "r"(a));
}
__device__ __forceinline__ void mma16816(float* c, const uint32_t* a,
                                         const uint32_t* b) {
    asm volatile("mma.sync.aligned.m16n8k16.row.col.f32.f16.f16.f32 "
                 "{%0,%1,%2,%3}, {%4,%5,%6,%7}, {%8,%9}, {%0,%1,%2,%3};"
                 : "+f"(c[0]), "+f"(c[1]), "+f"(c[2]), "+f"(c[3])
                 : "r"(a[0]), "r"(a[1]), "r"(a[2]), "r"(a[3]),
                   "r"(b[0]), "r"(b[1]));
}

// ---------------- kernel 1: init max buffers + per-batch lengths -------------
__global__ void prep_kernel(const int* __restrict__ mask1,
                            const int* __restrict__ mask2) {
    int tid = threadIdx.x;
    int gid = blockIdx.x * blockDim.x + tid;
    if (gid < BS) { g_rowmax[gid] = 0u; g_colmax[gid] = 0u; }

    if (blockIdx.x < 2 * Bn) {
        const int* row = (blockIdx.x < Bn) ? (mask1 + blockIdx.x * Sn)
                                           : (mask2 + (blockIdx.x - Bn) * Sn);
        int s = row[tid] + row[tid + 256];
        __shared__ int sh[256];
        sh[tid] = s;
        __syncthreads();
        for (int off = 128; off > 0; off >>= 1) {
            if (tid < off) sh[tid] += sh[tid + off];
            __syncthreads();
        }
        if (tid == 0) g_len[blockIdx.x] = sh[0];
    }
}

// ---------------- kernel 2: normalize -> fp16 (one warp per token) -----------
__global__ void norm_kernel(const float* __restrict__ e1,
                            const float* __restrict__ e2) {
    int warp = blockIdx.x * 8 + (threadIdx.x >> 5);
    int lane = threadIdx.x & 31;
    bool isA = (warp < BS);
    const float* p = isA ? (e1 + (size_t)warp * Dn)
                         : (e2 + (size_t)(warp - BS) * Dn);
    __half* dst = isA ? (g_hA + (size_t)warp * Dn)
                      : (g_hB + (size_t)(warp - BS) * Dn);
    const float4* p4 = (const float4*)p;
    float4 v[4];
    float ss = 0.f;
#pragma unroll
    for (int i = 0; i < 4; i++) {
        v[i] = p4[i * 32 + lane];
        ss += v[i].x * v[i].x + v[i].y * v[i].y + v[i].z * v[i].z + v[i].w * v[i].w;
    }
#pragma unroll
    for (int off = 16; off > 0; off >>= 1)
        ss += __shfl_xor_sync(0xffffffffu, ss, off);
    float inv = 1.0f / fmaxf(sqrtf(ss), 1e-8f);
    __half2* d2 = (__half2*)dst;
#pragma unroll
    for (int i = 0; i < 4; i++) {
        int e = i * 32 + lane;
        d2[e * 2 + 0] = __floats2half2_rn(v[i].x * inv, v[i].y * inv);
        d2[e * 2 + 1] = __floats2half2_rn(v[i].z * inv, v[i].w * inv);
    }
}

// ---------------- kernel 3: fp16 tensor-core sim + masked row/col max --------
// grid: (i_tiles=4, B=64); 256 threads = 8 warps (2 m x 4 n); tile 128x128, K-chunk 32
#define KP 40   // padded row length in halves (80 bytes) -> conflict-free ldmatrix
__global__ __launch_bounds__(256, 2) void sim_mma_kernel() {
    const int it = blockIdx.x;
    const int b  = blockIdx.y;
    const int n1 = g_len[b];
    const int n2 = g_len[Bn + b];
    if (it * 128 >= n1) return;

    __shared__ __half As[2][128][KP];
    __shared__ __half Bs[2][128][KP];

    const int tid  = threadIdx.x;
    const int wid  = tid >> 5;
    const int lane = tid & 31;
    const int wm   = wid & 1;        // 0..1 : 64-row slice
    const int wn   = wid >> 1;       // 0..3 : 32-col slice

    const __half* gA = g_hA + (size_t)(b * Sn + it * 128) * Dn;
    const __half* gB = g_hB + (size_t)b * Sn * Dn;

    const uint32_t sA = smem_u32(As);
    const uint32_t sB = smem_u32(Bs);

    // cp.async mapping: 512 chunks of 16B per tile; 2 per thread
    const int r0c = tid >> 1;              // not used; explicit idx loop below

    // per-lane running row maxes: rows wm*64 + mi*16 + (lane>>2) + h*8
    float rmax[4][2];
#pragma unroll
    for (int mi = 0; mi < 4; mi++) { rmax[mi][0] = -3e38f; rmax[mi][1] = -3e38f; }

    const int njt = (n2 + 127) >> 7;
    for (int jt = 0; jt < njt; jt++) {
        const __half* gBj = gB + (size_t)jt * 128 * Dn;

        float acc[4][4][4];
#pragma unroll
        for (int mi = 0; mi < 4; mi++)
#pragma unroll
            for (int nf = 0; nf < 4; nf++)
#pragma unroll
                for (int q = 0; q < 4; q++) acc[mi][nf][q] = 0.f;

        // prologue: load k-chunk 0 into buf 0
#pragma unroll
        for (int t = 0; t < 2; t++) {
            int idx = tid + t * 256;
            int r = idx >> 2, c = idx & 3;
            cp16(sA + (uint32_t)((0 * 128 + r) * KP + c * 8) * 2,
                 gA + (size_t)r * Dn + c * 8);
            cp16(sB + (uint32_t)((0 * 128 + r) * KP + c * 8) * 2,
                 gBj + (size_t)r * Dn + c * 8);
        }
        CP_COMMIT();

        for (int kc = 0; kc < 16; kc++) {
            int buf = kc & 1;
            if (kc + 1 < 16) {
                int nb = 1 - buf;
                int k0 = (kc + 1) * 32;
#pragma unroll
                for (int t = 0; t < 2; t++) {
                    int idx = tid + t * 256;
                    int r = idx >> 2, c = idx & 3;
                    cp16(sA + (uint32_t)((nb * 128 + r) * KP + c * 8) * 2,
                         gA + (size_t)r * Dn + k0 + c * 8);
                    cp16(sB + (uint32_t)((nb * 128 + r) * KP + c * 8) * 2,
                         gBj + (size_t)r * Dn + k0 + c * 8);
                }
                CP_COMMIT();
                CP_WAIT(1);
            } else {
                CP_WAIT(0);
            }
            __syncthreads();

#pragma unroll
            for (int ks = 0; ks < 2; ks++) {
                uint32_t ra[4][4];
#pragma unroll
                for (int mi = 0; mi < 4; mi++) {
                    int row = wm * 64 + mi * 16 + (lane & 15);
                    int col = ks * 16 + ((lane >> 4) << 3);
                    ldm_x4(ra[mi][0], ra[mi][1], ra[mi][2], ra[mi][3],
                           sA + (uint32_t)((buf * 128 + row) * KP + col) * 2);
                }
                uint32_t rb[2][4];
#pragma unroll
                for (int np = 0; np < 2; np++) {
                    int row = wn * 32 + np * 16 + (lane & 7) + ((lane & 16) ? 8 : 0);
                    int col = ks * 16 + ((lane & 8) ? 8 : 0);
                    ldm_x4(rb[np][0], rb[np][1], rb[np][2], rb[np][3],
                           sB + (uint32_t)((buf * 128 + row) * KP + col) * 2);
                }
#pragma unroll
                for (int mi = 0; mi < 4; mi++) {
#pragma unroll
                    for (int np = 0; np < 2; np++) {
                        mma16816(acc[mi][np * 2 + 0], ra[mi], &rb[np][0]);
                        mma16816(acc[mi][np * 2 + 1], ra[mi], &rb[np][2]);
                    }
                }
            }
            __syncthreads();
        }

        // ---- epilogue for this j-tile ----
        // col-max: mask rows (i<n1), reduce lanes sharing same col, atomicMax
#pragma unroll
        for (int nf = 0; nf < 4; nf++) {
            float cm0 = -3e38f, cm1 = -3e38f;
#pragma unroll
            for (int mi = 0; mi < 4; mi++) {
#pragma unroll
                for (int h = 0; h < 2; h++) {
                    int gi = it * 128 + wm * 64 + mi * 16 + (lane >> 2) + h * 8;
                    if (gi < n1) {
                        cm0 = fmaxf(cm0, acc[mi][nf][h * 2 + 0]);
                        cm1 = fmaxf(cm1, acc[mi][nf][h * 2 + 1]);
                    }
                }
            }
#pragma unroll
            for (int off = 4; off < 32; off <<= 1) {
                cm0 = fmaxf(cm0, __shfl_xor_sync(0xffffffffu, cm0, off));
                cm1 = fmaxf(cm1, __shfl_xor_sync(0xffffffffu, cm1, off));
            }
            if (lane < 4) {
                int j = jt * 128 + wn * 32 + nf * 8 + lane * 2;
                if (j < n2)     atomicMax(&g_colmax[b * Sn + j], encf(cm0));
                if (j + 1 < n2) atomicMax(&g_colmax[b * Sn + j + 1], encf(cm1));
            }
        }
        // row-max: mask cols (j<n2), fold into running per-lane row maxes
#pragma unroll
        for (int mi = 0; mi < 4; mi++) {
#pragma unroll
            for (int h = 0; h < 2; h++) {
                float v = -3e38f;
#pragma unroll
                for (int nf = 0; nf < 4; nf++) {
                    int j = jt * 128 + wn * 32 + nf * 8 + (lane & 3) * 2;
                    if (j < n2)     v = fmaxf(v, acc[mi][nf][h * 2 + 0]);
                    if (j + 1 < n2) v = fmaxf(v, acc[mi][nf][h * 2 + 1]);
                }
                rmax[mi][h] = fmaxf(rmax[mi][h], v);
            }
        }
        __syncthreads();   // before next j-tile overwrites buf 0
    }

    // final row-max: reduce lanes sharing same row (l^1, l^2), then atomicMax
#pragma unroll
    for (int mi = 0; mi < 4; mi++) {
#pragma unroll
        for (int h = 0; h < 2; h++) {
            float v = rmax[mi][h];
            v = fmaxf(v, __shfl_xor_sync(0xffffffffu, v, 1));
            v = fmaxf(v, __shfl_xor_sync(0xffffffffu, v, 2));
            if ((lane & 3) == 0) {
                int gi = it * 128 + wm * 64 + mi * 16 + (lane >> 2) + h * 8;
                if (gi < n1) atomicMax(&g_rowmax[b * Sn + gi], encf(v));
            }
        }
    }
}

// ---------------- kernel 4: per-batch reduction ------------------------------
__global__ void reduce_kernel(float* __restrict__ out) {
    int b = blockIdx.x;
    int tid = threadIdx.x;
    int n1 = g_len[b], n2 = g_len[Bn + b];
    float s = 0.f;
    for (int i = tid; i < n1; i += 256) s += decf(g_rowmax[b * Sn + i]);
    for (int j = tid; j < n2; j += 256) s += decf(g_colmax[b * Sn + j]);
    __shared__ float sh[256];
    sh[tid] = s;
    __syncthreads();
    for (int off = 128; off > 0; off >>= 1) {
        if (tid < off) sh[tid] += sh[tid + off];
        __syncthreads();
    }
    if (tid == 0) out[b] = sh[0] / (float)(n1 + n2);
}

// ---------------- launch -----------------------------------------------------
extern "C" void kernel_launch(void* const* d_in, const int* in_sizes, int n_in,
                              void* d_out, int out_size) {
    const float* e1 = (const float*)d_in[0];
    const float* e2 = (const float*)d_in[1];
    const int* m1 = (const int*)d_in[2];
    const int* m2 = (const int*)d_in[3];
    float* out = (float*)d_out;

    prep_kernel<<<256, 256>>>(m1, m2);
    norm_kernel<<<(2 * BS) / 8, 256>>>(e1, e2);
    dim3 grid(Sn / 128, Bn);
    sim_mma_kernel<<<grid, 256>>>();
    reduce_kernel<<<Bn, 256>>>(out);
}

// round 4
// speedup vs baseline: 4.8201x; 1.8196x over previous
#include <cuda_runtime.h>
#include <cuda_fp16.h>
#include <cstdint>

// Problem constants (fixed shapes: B=64, S=512, D=512)
#define Bn 64
#define Sn 512
#define Dn 512
#define BS (Bn * Sn)

// ---------------- scratch (device globals; no allocations allowed) ----------
__device__ unsigned g_rowmax[BS];       // ordered-uint max over valid j per (b,i)
__device__ unsigned g_colmax[BS];       // ordered-uint max over valid i per (b,j)
__device__ int      g_len[2 * Bn];      // n1[b], then n2[b]
__device__ __half   g_hA[BS * Dn];      // normalized e1, fp16 (32MB), invalid rows = 0
__device__ __half   g_hB[BS * Dn];      // normalized e2, fp16 (32MB), invalid rows = 0

// ordered encoding: monotonic float -> uint, so atomicMax(unsigned) == float max
__device__ __forceinline__ unsigned encf(float x) {
    unsigned u = __float_as_uint(x);
    return (u & 0x80000000u) ? ~u : (u | 0x80000000u);
}
__device__ __forceinline__ float decf(unsigned u) {
    return (u & 0x80000000u) ? __uint_as_float(u ^ 0x80000000u)
                             : __uint_as_float(~u);
}

// ---------------- async-copy / mma helpers (sm_80+ PTX, compute_103-safe) ----
__device__ __forceinline__ uint32_t smem_u32(const void* p) {
    uint32_t a;
    asm("{ .reg .u64 t; cvta.to.shared.u64 t, %1; cvt.u32.u64 %0, t; }"
        : "=r"(a) : "l"(p));
    return a;
}
__device__ __forceinline__ void cp16(uint32_t s, const void* g) {
    asm volatile("cp.async.ca.shared.global [%0], [%1], 16;" :: "r"(s), "l"(g));
}
#define CP_COMMIT() asm volatile("cp.async.commit_group;" ::: "memory")
#define CP_WAIT(N)  asm volatile("cp.async.wait_group %0;" :: "n"(N) : "memory")

__device__ __forceinline__ void ldm_x4(uint32_t& r0, uint32_t& r1,
                                       uint32_t& r2, uint32_t& r3, uint32_t a) {
    asm volatile("ldmatrix.sync.aligned.m8n8.x4.shared.b16 {%0,%1,%2,%3}, [%4];"
                 : "=r"(r0), "=r"(r1), "=r"(r2), "=r"(r3) : "r"(a));
}
__device__ __forceinline__ void mma16816(float* c, const uint32_t* a,
                                         const uint32_t* b) {
    asm volatile("mma.sync.aligned.m16n8k16.row.col.f32.f16.f16.f32 "
                 "{%0,%1,%2,%3}, {%4,%5,%6,%7}, {%8,%9}, {%0,%1,%2,%3};"
                 : "+f"(c[0]), "+f"(c[1]), "+f"(c[2]), "+f"(c[3])
                 : "r"(a[0]), "r"(a[1]), "r"(a[2]), "r"(a[3]),
                   "r"(b[0]), "r"(b[1]));
}

// ---------------- kernel 1: init max buffers + per-batch lengths -------------
__global__ void prep_kernel(const int* __restrict__ mask1,
                            const int* __restrict__ mask2) {
    int tid = threadIdx.x;
    int gid = blockIdx.x * blockDim.x + tid;
    if (gid < BS) { g_rowmax[gid] = 0u; g_colmax[gid] = 0u; }

    if (blockIdx.x < 2 * Bn) {
        const int* row = (blockIdx.x < Bn) ? (mask1 + blockIdx.x * Sn)
                                           : (mask2 + (blockIdx.x - Bn) * Sn);
        int s = row[tid] + row[tid + 256];
        __shared__ int sh[256];
        sh[tid] = s;
        __syncthreads();
        for (int off = 128; off > 0; off >>= 1) {
            if (tid < off) sh[tid] += sh[tid + off];
            __syncthreads();
        }
        if (tid == 0) g_len[blockIdx.x] = sh[0];
    }
}

// ---------------- kernel 2: normalize valid tokens -> fp16 -------------------
// one warp per token; warps whose token is masked out exit immediately.
__global__ void norm_kernel(const float* __restrict__ e1,
                            const float* __restrict__ e2) {
    int warp = blockIdx.x * 8 + (threadIdx.x >> 5);
    int lane = threadIdx.x & 31;
    bool isA = (warp < BS);
    int t = isA ? warp : warp - BS;
    int b = t >> 9, s = t & (Sn - 1);
    if (s >= g_len[b + (isA ? 0 : Bn)]) return;   // invalid token: scratch stays 0

    const float* p = isA ? (e1 + (size_t)t * Dn) : (e2 + (size_t)t * Dn);
    __half* dst = isA ? (g_hA + (size_t)t * Dn) : (g_hB + (size_t)t * Dn);
    const float4* p4 = (const float4*)p;
    float4 v[4];
    float ss = 0.f;
#pragma unroll
    for (int i = 0; i < 4; i++) {
        v[i] = p4[i * 32 + lane];
        ss += v[i].x * v[i].x + v[i].y * v[i].y + v[i].z * v[i].z + v[i].w * v[i].w;
    }
#pragma unroll
    for (int off = 16; off > 0; off >>= 1)
        ss += __shfl_xor_sync(0xffffffffu, ss, off);
    float inv = 1.0f / fmaxf(sqrtf(ss), 1e-8f);
    __half2* d2 = (__half2*)dst;
#pragma unroll
    for (int i = 0; i < 4; i++) {
        int e = i * 32 + lane;
        d2[e * 2 + 0] = __floats2half2_rn(v[i].x * inv, v[i].y * inv);
        d2[e * 2 + 1] = __floats2half2_rn(v[i].z * inv, v[i].w * inv);
    }
}

// ---------------- kernel 3: fp16 tensor-core sim + masked row/col max --------
// grid (jt=4, it=4, b=64): one 128x128x512 tile pair per block. 8 warps (2m x 4n).
// 3-stage cp.async pipeline, K-chunk 32, one __syncthreads per chunk.
#define KP 40                          // padded row (80B): conflict-free ldmatrix
#define BUF_H (128 * KP)               // halves per buffer per array
__global__ __launch_bounds__(256, 2) void sim_mma_kernel() {
    const int jt = blockIdx.x;
    const int it = blockIdx.y;
    const int b  = blockIdx.z;
    const int n1 = g_len[b];
    const int n2 = g_len[Bn + b];
    if (it * 128 >= n1 || jt * 128 >= n2) return;

    extern __shared__ __half sm[];      // [3][128][KP] A, then [3][128][KP] B
    __half* smA = sm;
    __half* smB = sm + 3 * BUF_H;

    const int tid  = threadIdx.x;
    const int wid  = tid >> 5;
    const int lane = tid & 31;
    const int wm   = wid & 1;          // 0..1 : 64-row slice
    const int wn   = wid >> 1;         // 0..3 : 32-col slice

    const __half* gA = g_hA + (size_t)(b * Sn + it * 128) * Dn;
    const __half* gB = g_hB + (size_t)(b * Sn + jt * 128) * Dn;
    const uint32_t sA = smem_u32(smA);
    const uint32_t sB = smem_u32(smB);

    // cp.async mapping: thread -> 2 (row, 16B-col) pairs per array per chunk
    const int cr0 = tid >> 2, cc0 = (tid & 3) * 8;           // rows 0..63
    const int cr1 = cr0 + 64;                                 // rows 64..127

    float acc[4][4][4];
#pragma unroll
    for (int mi = 0; mi < 4; mi++)
#pragma unroll
        for (int nf = 0; nf < 4; nf++)
#pragma unroll
            for (int q = 0; q < 4; q++) acc[mi][nf][q] = 0.f;

#define PREFETCH(KC, S) do {                                                   \
    int k0_ = (KC) * 32;                                                       \
    uint32_t ba_ = sA + (uint32_t)((S) * BUF_H) * 2;                           \
    uint32_t bb_ = sB + (uint32_t)((S) * BUF_H) * 2;                           \
    cp16(ba_ + (uint32_t)(cr0 * KP + cc0) * 2, gA + (size_t)cr0 * Dn + k0_ + cc0); \
    cp16(ba_ + (uint32_t)(cr1 * KP + cc0) * 2, gA + (size_t)cr1 * Dn + k0_ + cc0); \
    cp16(bb_ + (uint32_t)(cr0 * KP + cc0) * 2, gB + (size_t)cr0 * Dn + k0_ + cc0); \
    cp16(bb_ + (uint32_t)(cr1 * KP + cc0) * 2, gB + (size_t)cr1 * Dn + k0_ + cc0); \
} while (0)

    // prologue: stages for chunks 0 and 1
    PREFETCH(0, 0); CP_COMMIT();
    PREFETCH(1, 1); CP_COMMIT();

    for (int kc = 0; kc < 16; kc++) {
        if (kc < 15) CP_WAIT(1); else CP_WAIT(0);
        __syncthreads();
        if (kc + 2 < 16) { PREFETCH(kc + 2, (kc + 2) % 3); CP_COMMIT(); }

        const int buf = kc % 3;
        const uint32_t bA = sA + (uint32_t)(buf * BUF_H) * 2;
        const uint32_t bB = sB + (uint32_t)(buf * BUF_H) * 2;
#pragma unroll
        for (int ks = 0; ks < 2; ks++) {
            uint32_t ra[4][4];
#pragma unroll
            for (int mi = 0; mi < 4; mi++) {
                int row = wm * 64 + mi * 16 + (lane & 15);
                int col = ks * 16 + ((lane >> 4) << 3);
                ldm_x4(ra[mi][0], ra[mi][1], ra[mi][2], ra[mi][3],
                       bA + (uint32_t)(row * KP + col) * 2);
            }
            uint32_t rb[2][4];
#pragma unroll
            for (int np = 0; np < 2; np++) {
                int row = wn * 32 + np * 16 + (lane & 7) + ((lane & 16) ? 8 : 0);
                int col = ks * 16 + ((lane & 8) ? 8 : 0);
                ldm_x4(rb[np][0], rb[np][1], rb[np][2], rb[np][3],
                       bB + (uint32_t)(row * KP + col) * 2);
            }
#pragma unroll
            for (int mi = 0; mi < 4; mi++) {
#pragma unroll
                for (int np = 0; np < 2; np++) {
                    mma16816(acc[mi][np * 2 + 0], ra[mi], &rb[np][0]);
                    mma16816(acc[mi][np * 2 + 1], ra[mi], &rb[np][2]);
                }
            }
        }
    }

    // ---- epilogue ----
    // col-max: mask rows (i<n1), reduce lanes sharing col, atomicMax to global
#pragma unroll
    for (int nf = 0; nf < 4; nf++) {
        float cm0 = -3e38f, cm1 = -3e38f;
#pragma unroll
        for (int mi = 0; mi < 4; mi++) {
#pragma unroll
            for (int h = 0; h < 2; h++) {
                int gi = it * 128 + wm * 64 + mi * 16 + (lane >> 2) + h * 8;
                if (gi < n1) {
                    cm0 = fmaxf(cm0, acc[mi][nf][h * 2 + 0]);
                    cm1 = fmaxf(cm1, acc[mi][nf][h * 2 + 1]);
                }
            }
        }
#pragma unroll
        for (int off = 4; off < 32; off <<= 1) {
            cm0 = fmaxf(cm0, __shfl_xor_sync(0xffffffffu, cm0, off));
            cm1 = fmaxf(cm1, __shfl_xor_sync(0xffffffffu, cm1, off));
        }
        if (lane < 4) {
            int j = jt * 128 + wn * 32 + nf * 8 + lane * 2;
            if (j < n2)     atomicMax(&g_colmax[b * Sn + j], encf(cm0));
            if (j + 1 < n2) atomicMax(&g_colmax[b * Sn + j + 1], encf(cm1));
        }
    }
    // row-max: mask cols (j<n2), reduce lanes sharing row, atomicMax to global
#pragma unroll
    for (int mi = 0; mi < 4; mi++) {
#pragma unroll
        for (int h = 0; h < 2; h++) {
            float v = -3e38f;
#pragma unroll
            for (int nf = 0; nf < 4; nf++) {
                int j = jt * 128 + wn * 32 + nf * 8 + (lane & 3) * 2;
                if (j < n2)     v = fmaxf(v, acc[mi][nf][h * 2 + 0]);
                if (j + 1 < n2) v = fmaxf(v, acc[mi][nf][h * 2 + 1]);
            }
            v = fmaxf(v, __shfl_xor_sync(0xffffffffu, v, 1));
            v = fmaxf(v, __shfl_xor_sync(0xffffffffu, v, 2));
            if ((lane & 3) == 0) {
                int gi = it * 128 + wm * 64 + mi * 16 + (lane >> 2) + h * 8;
                if (gi < n1) atomicMax(&g_rowmax[b * Sn + gi], encf(v));
            }
        }
    }
}

// ---------------- kernel 4: per-batch reduction ------------------------------
__global__ void reduce_kernel(float* __restrict__ out) {
    int b = blockIdx.x;
    int tid = threadIdx.x;
    int n1 = g_len[b], n2 = g_len[Bn + b];
    float s = 0.f;
    for (int i = tid; i < n1; i += 256) s += decf(g_rowmax[b * Sn + i]);
    for (int j = tid; j < n2; j += 256) s += decf(g_colmax[b * Sn + j]);
    __shared__ float sh[256];
    sh[tid] = s;
    __syncthreads();
    for (int off = 128; off > 0; off >>= 1) {
        if (tid < off) sh[tid] += sh[tid + off];
        __syncthreads();
    }
    if (tid == 0) out[b] = sh[0] / (float)(n1 + n2);
}

// ---------------- launch -----------------------------------------------------
#define SMEM_BYTES (6 * BUF_H * 2)    // 3 stages x (A + B) x 128x40 halves = 60KB

extern "C" void kernel_launch(void* const* d_in, const int* in_sizes, int n_in,
                              void* d_out, int out_size) {
    const float* e1 = (const float*)d_in[0];
    const float* e2 = (const float*)d_in[1];
    const int* m1 = (const int*)d_in[2];
    const int* m2 = (const int*)d_in[3];
    float* out = (float*)d_out;

    static int attr_done = 0;
    if (!attr_done) {
        cudaFuncSetAttribute(sim_mma_kernel,
                             cudaFuncAttributeMaxDynamicSharedMemorySize, SMEM_BYTES);
        attr_done = 1;
    }

    prep_kernel<<<256, 256>>>(m1, m2);
    norm_kernel<<<(2 * BS) / 8, 256>>>(e1, e2);
    dim3 grid(4, 4, Bn);
    sim_mma_kernel<<<grid, 256, SMEM_BYTES>>>();
    reduce_kernel<<<Bn, 256>>>(out);
}